// round 5
// baseline (speedup 1.0000x reference)
#include <cuda_runtime.h>
#include <cuda_bf16.h>
#include <math.h>

// Problem constants: N=50000 nodes, E=800000 edges, F=64, HID=64, OUT=32
#define MAXN 50176      // padded to 49*1024
#define MAXE 800000

// ---------- device scratch (no allocations allowed) ----------
__device__ __align__(16) float g_deg[MAXN];
__device__ __align__(16) float g_dinv[MAXN];
__device__ __align__(16) int   g_count[MAXN];
__device__ __align__(16) int   g_cursor[MAXN];
__device__ __align__(16) int   g_offs[MAXN];
__device__ __align__(16) int   g_bsum[64];
__device__ __align__(16) int   g_bpref[64];
__device__ __align__(16) int   g_srcs[MAXE];
__device__ __align__(16) float g_coef[MAXE];
__device__ __align__(16) float g_px[MAXN * 64];
__device__ int g_is64;   // 1 if edge_index is int64, 0 if int32

// ---------- K0: detect edge_index dtype ----------
// If int64 (values < 2^31), every odd 32-bit word is 0. If int32, the odd
// words are actual random node indices — P(all 128 zero) ~ 0.
__global__ void k_detect(const int* __restrict__ ei32, int e2) {
    __shared__ int any;
    if (threadIdx.x == 0) any = 0;
    __syncthreads();
    int idx = 2 * threadIdx.x + 1;
    if (idx < e2 && ei32[idx] != 0) atomicOr(&any, 1);
    __syncthreads();
    if (threadIdx.x == 0) g_is64 = (any == 0) ? 1 : 0;
}

__device__ __forceinline__ int load_idx(const void* ei, int pos) {
    if (g_is64) return (int)((const long long*)ei)[pos];
    return ((const int*)ei)[pos];
}
__device__ __forceinline__ int clampi(int v, int n) {
    return ((unsigned)v < (unsigned)n) ? v : 0;
}

// ---------- K1: zero per-node scratch ----------
__global__ void k_zero(int n) {
    int i = blockIdx.x * blockDim.x + threadIdx.x;
    if (i < n) { g_deg[i] = 0.f; g_count[i] = 0; g_cursor[i] = 0; }
}

// ---------- K2: degree (by src) + per-dst edge count ----------
__global__ void k_edge1(const void* __restrict__ ei, const float* __restrict__ ew, int e, int n) {
    int i = blockIdx.x * blockDim.x + threadIdx.x;
    if (i < e) {
        int s = clampi(load_idx(ei, i), n);
        int d = clampi(load_idx(ei, e + i), n);
        atomicAdd(&g_deg[s], ew[i]);
        atomicAdd(&g_count[d], 1);
    }
}

// ---------- K3: dinv ----------
__global__ void k_dinv(int n) {
    int i = blockIdx.x * blockDim.x + threadIdx.x;
    if (i < n) {
        float dg = g_deg[i];
        g_dinv[i] = (dg > 0.f) ? rsqrtf(dg) : 0.f;
    }
}

// ---------- scan (block-local exclusive) ----------
__global__ void k_scan_block(int n) {
    __shared__ int sh[1024];
    int t = threadIdx.x;
    int i = blockIdx.x * 1024 + t;
    int v = (i < n) ? g_count[i] : 0;
    sh[t] = v;
    __syncthreads();
    for (int d = 1; d < 1024; d <<= 1) {
        int add = (t >= d) ? sh[t - d] : 0;
        __syncthreads();
        sh[t] += add;
        __syncthreads();
    }
    int incl = sh[t];
    if (i < n) g_offs[i] = incl - v;
    if (t == 1023) g_bsum[blockIdx.x] = incl;
}

__global__ void k_scan_bsum(int nb) {
    __shared__ int sh[64];
    int t = threadIdx.x;
    int v = (t < nb) ? g_bsum[t] : 0;
    sh[t] = v;
    __syncthreads();
    for (int d = 1; d < 64; d <<= 1) {
        int add = (t >= d) ? sh[t - d] : 0;
        __syncthreads();
        sh[t] += add;
        __syncthreads();
    }
    g_bpref[t] = sh[t] - v;
}

// ---------- K4: bucket fill (CSR) with normalized coefficient ----------
__global__ void k_edge2(const void* __restrict__ ei, const float* __restrict__ ew, int e, int n) {
    int i = blockIdx.x * blockDim.x + threadIdx.x;
    if (i < e) {
        int s = clampi(load_idx(ei, i), n);
        int d = clampi(load_idx(ei, e + i), n);
        int pos = g_offs[d] + g_bpref[d >> 10] + atomicAdd(&g_cursor[d], 1);
        pos = clampi(pos, e);
        g_srcs[pos] = s;
        g_coef[pos] = -g_dinv[s] * ew[i] * g_dinv[d];
    }
}

// ---------- K5: propagation px[dst] = sum coef * x[src], one warp per dst ----------
__global__ void k_prop(const float* __restrict__ x, int n) {
    int gw = (blockIdx.x * blockDim.x + threadIdx.x) >> 5;
    int lane = threadIdx.x & 31;
    if (gw >= n) return;
    int start = g_offs[gw] + g_bpref[gw >> 10];
    int m = g_count[gw];
    float a0 = 0.f, a1 = 0.f;
    for (int j = 0; j < m; j++) {
        int s = __ldg(&g_srcs[start + j]);
        float c = __ldg(&g_coef[start + j]);
        const float* xr = x + (size_t)s * 64;
        a0 = fmaf(c, __ldg(&xr[lane]), a0);
        a1 = fmaf(c, __ldg(&xr[lane + 32]), a1);
    }
    g_px[(size_t)gw * 64 + lane] = a0;
    g_px[(size_t)gw * 64 + 32 + lane] = a1;
}

// ---------- K6: fused [x|px]@Wzh -> gate -> @Wlin -> L2-normalize ----------
#define TM 32
__global__ __launch_bounds__(256, 2) void k_fused(
    const float* __restrict__ x,
    const float* __restrict__ Wxz0, const float* __restrict__ Wxz1,
    const float* __restrict__ bxz,  const float* __restrict__ bhz,
    const float* __restrict__ Wxh0, const float* __restrict__ Wxh1,
    const float* __restrict__ bxh,  const float* __restrict__ bhh,
    const float* __restrict__ Wlin, const float* __restrict__ blin,
    float* __restrict__ out, int n)
{
    extern __shared__ __align__(16) float sh[];
    float* sW   = sh;                 // 128*128 = 16384
    float* sWl  = sW + 16384;         // 64*32   = 2048
    float* sB   = sWl + 2048;         // 128
    float* sBl  = sB + 128;           // 32
    float* sIN  = sBl + 32;           // 32*128  = 4096
    float* sU   = sIN + 4096;         // 32*64   = 2048
    // total 24736 floats = 98944 bytes

    int tid = threadIdx.x;

    for (int idx = tid; idx < 16384; idx += 256) {
        int k = idx >> 7, o = idx & 127;
        float v;
        if (k < 64) v = (o < 64) ? Wxz0[k * 64 + o] : Wxh0[k * 64 + (o - 64)];
        else        v = (o < 64) ? Wxz1[(k - 64) * 64 + o] : Wxh1[(k - 64) * 64 + (o - 64)];
        sW[idx] = v;
    }
    for (int idx = tid; idx < 2048; idx += 256) sWl[idx] = Wlin[idx];
    if (tid < 128) sB[tid] = (tid < 64) ? (bxz[tid] + bhz[tid]) : (bxh[tid - 64] + bhh[tid - 64]);
    if (tid < 32) sBl[tid] = blin[tid];

    int node0 = blockIdx.x * TM;

    for (int idx = tid; idx < TM * 32; idx += 256) {
        int r = idx >> 5, c4 = idx & 31;
        int node = node0 + r;
        float4 v = make_float4(0.f, 0.f, 0.f, 0.f);
        if (node < n) {
            if (c4 < 16) v = reinterpret_cast<const float4*>(x)[(size_t)node * 16 + c4];
            else         v = reinterpret_cast<const float4*>(g_px)[(size_t)node * 16 + (c4 - 16)];
        }
        reinterpret_cast<float4*>(sIN)[idx] = v;
    }
    __syncthreads();

    int og = tid & 31;
    int ng = tid >> 5;
    int obase = og * 4;
    float acc[4][4];
#pragma unroll
    for (int i = 0; i < 4; i++)
#pragma unroll
        for (int j = 0; j < 4; j++) acc[i][j] = sB[obase + j];

#pragma unroll 4
    for (int k = 0; k < 128; k++) {
        float4 w = *reinterpret_cast<const float4*>(&sW[k * 128 + obase]);
#pragma unroll
        for (int i = 0; i < 4; i++) {
            float in = sIN[(ng + i * 8) * 128 + k];
            acc[i][0] = fmaf(in, w.x, acc[i][0]);
            acc[i][1] = fmaf(in, w.y, acc[i][1]);
            acc[i][2] = fmaf(in, w.z, acc[i][2]);
            acc[i][3] = fmaf(in, w.w, acc[i][3]);
        }
    }
    __syncthreads();
#pragma unroll
    for (int i = 0; i < 4; i++) {
        int r = ng + i * 8;
#pragma unroll
        for (int j = 0; j < 4; j++) sIN[r * 128 + obase + j] = acc[i][j];
    }
    __syncthreads();

    for (int idx = tid; idx < TM * 64; idx += 256) {
        int r = idx >> 6, j = idx & 63;
        float zp = sIN[r * 128 + j];
        float hp = sIN[r * 128 + 64 + j];
        float z = 1.f / (1.f + __expf(-zp));
        sU[idx] = (1.f - z) * tanhf(hp);
    }
    __syncthreads();

    int node = tid >> 3;
    int og2 = tid & 7;
    int ob = og2 * 4;
    float a0 = sBl[ob], a1 = sBl[ob + 1], a2 = sBl[ob + 2], a3 = sBl[ob + 3];
#pragma unroll 8
    for (int k = 0; k < 64; k++) {
        float u = sU[node * 64 + k];
        float4 w = *reinterpret_cast<const float4*>(&sWl[k * 32 + ob]);
        a0 = fmaf(u, w.x, a0);
        a1 = fmaf(u, w.y, a1);
        a2 = fmaf(u, w.z, a2);
        a3 = fmaf(u, w.w, a3);
    }
    float ss = a0 * a0 + a1 * a1 + a2 * a2 + a3 * a3;
    ss += __shfl_xor_sync(0xffffffffu, ss, 1);
    ss += __shfl_xor_sync(0xffffffffu, ss, 2);
    ss += __shfl_xor_sync(0xffffffffu, ss, 4);
    float scale = 1.f / fmaxf(sqrtf(ss), 1e-12f);
    int gnode = node0 + node;
    if (gnode < n) {
        float4 o4 = make_float4(a0 * scale, a1 * scale, a2 * scale, a3 * scale);
        reinterpret_cast<float4*>(out)[(size_t)gnode * 8 + og2] = o4;
    }
}

extern "C" void kernel_launch(void* const* d_in, const int* in_sizes, int n_in,
                              void* d_out, int out_size) {
    const float* x    = (const float*)d_in[0];
    const void*  ei   = d_in[1];
    const float* ew   = (const float*)d_in[2];
    const float* Wxz0 = (const float*)d_in[3];
    const float* Wxz1 = (const float*)d_in[4];
    const float* bxz  = (const float*)d_in[5];
    const float* bhz  = (const float*)d_in[8];
    const float* Wxh0 = (const float*)d_in[15];
    const float* Wxh1 = (const float*)d_in[16];
    const float* bxh  = (const float*)d_in[17];
    const float* bhh  = (const float*)d_in[20];
    const float* Wlin = (const float*)d_in[21];
    const float* blin = (const float*)d_in[22];
    float* out = (float*)d_out;

    int n = in_sizes[0] / 64;   // 50000
    int e = in_sizes[2];        // 800000

    static int s_attr_done = 0;
    if (!s_attr_done) {
        cudaFuncSetAttribute(k_fused, cudaFuncAttributeMaxDynamicSharedMemorySize, 98944);
        s_attr_done = 1;
    }

    int nbN = (n + 255) / 256;
    int nbE = (e + 255) / 256;
    int nbScan = (n + 1023) / 1024;

    k_detect<<<1, 128>>>((const int*)ei, in_sizes[1]);  // probe first words
    k_zero<<<nbN, 256>>>(n);
    k_edge1<<<nbE, 256>>>(ei, ew, e, n);
    k_dinv<<<nbN, 256>>>(n);
    k_scan_block<<<nbScan, 1024>>>(n);
    k_scan_bsum<<<1, 64>>>(nbScan);
    k_edge2<<<nbE, 256>>>(ei, ew, e, n);
    k_prop<<<(n * 32 + 255) / 256, 256>>>(x, n);
    k_fused<<<(n + TM - 1) / TM, 256, 98944>>>(
        x, Wxz0, Wxz1, bxz, bhz, Wxh0, Wxh1, bxh, bhh, Wlin, blin, out, n);
}

// round 6
// speedup vs baseline: 1.0225x; 1.0225x over previous
#include <cuda_runtime.h>
#include <cuda_bf16.h>
#include <math.h>

// Problem constants: N=50000 nodes, E=800000 edges, F=64, HID=64, OUT=32
#define MAXN 50176      // padded to 49*1024
#define MAXE 800008     // +8 pad: k_prop prefetches one past segment end

// ---------- device scratch (no allocations allowed) ----------
__device__ __align__(16) float g_deg[MAXN];
__device__ __align__(16) float g_dinv[MAXN];
__device__ __align__(16) int   g_count[MAXN];
__device__ __align__(16) int   g_cursor[MAXN];
__device__ __align__(16) int   g_offs[MAXN];
__device__ __align__(16) int   g_bsum[64];
__device__ __align__(16) int   g_bpref[64];
__device__ __align__(16) int2  g_pair[MAXE];   // (src, bitcast(coef)) interleaved
__device__ __align__(16) float g_px[MAXN * 64];
__device__ int g_is64;   // 1 if edge_index is int64, 0 if int32

__device__ __forceinline__ int load_idx(const void* ei, int pos) {
    if (g_is64) return (int)((const long long*)ei)[pos];
    return ((const int*)ei)[pos];
}
__device__ __forceinline__ int clampi(int v, int n) {
    return ((unsigned)v < (unsigned)n) ? v : 0;
}

// ---------- K1: zero per-node scratch + dtype detect (block 0) ----------
// int64 detection: small nonneg values -> every odd 32-bit word is 0.
__global__ void k_init(const int* __restrict__ ei32, int n) {
    int i = blockIdx.x * blockDim.x + threadIdx.x;
    if (i < n) { g_deg[i] = 0.f; g_count[i] = 0; g_cursor[i] = 0; }
    if (blockIdx.x == 0) {
        __shared__ int any;
        if (threadIdx.x == 0) any = 0;
        __syncthreads();
        if (threadIdx.x < 128 && ei32[2 * threadIdx.x + 1] != 0) atomicOr(&any, 1);
        __syncthreads();
        if (threadIdx.x == 0) g_is64 = (any == 0) ? 1 : 0;
    }
}

// ---------- K2: degree (by src) + per-dst edge count ----------
__global__ void k_edge1(const void* __restrict__ ei, const float* __restrict__ ew, int e, int n) {
    int i = blockIdx.x * blockDim.x + threadIdx.x;
    if (i < e) {
        int s = clampi(load_idx(ei, i), n);
        int d = clampi(load_idx(ei, e + i), n);
        atomicAdd(&g_deg[s], ew[i]);
        atomicAdd(&g_count[d], 1);
    }
}

// ---------- K3: dinv + block-local exclusive scan of counts ----------
__global__ void k_scan_dinv(int n) {
    __shared__ int sh[1024];
    int t = threadIdx.x;
    int i = blockIdx.x * 1024 + t;
    if (i < n) {
        float dg = g_deg[i];
        g_dinv[i] = (dg > 0.f) ? rsqrtf(dg) : 0.f;
    }
    int v = (i < n) ? g_count[i] : 0;
    sh[t] = v;
    __syncthreads();
    for (int d = 1; d < 1024; d <<= 1) {
        int add = (t >= d) ? sh[t - d] : 0;
        __syncthreads();
        sh[t] += add;
        __syncthreads();
    }
    int incl = sh[t];
    if (i < n) g_offs[i] = incl - v;
    if (t == 1023) g_bsum[blockIdx.x] = incl;
}

// ---------- K4: scan of block sums ----------
__global__ void k_scan_bsum(int nb) {
    __shared__ int sh[64];
    int t = threadIdx.x;
    int v = (t < nb) ? g_bsum[t] : 0;
    sh[t] = v;
    __syncthreads();
    for (int d = 1; d < 64; d <<= 1) {
        int add = (t >= d) ? sh[t - d] : 0;
        __syncthreads();
        sh[t] += add;
        __syncthreads();
    }
    g_bpref[t] = sh[t] - v;
}

// ---------- K5: bucket fill (CSR) with normalized coefficient ----------
__global__ void k_edge2(const void* __restrict__ ei, const float* __restrict__ ew, int e, int n) {
    int i = blockIdx.x * blockDim.x + threadIdx.x;
    if (i < e) {
        int s = clampi(load_idx(ei, i), n);
        int d = clampi(load_idx(ei, e + i), n);
        int pos = g_offs[d] + g_bpref[d >> 10] + atomicAdd(&g_cursor[d], 1);
        pos = clampi(pos, e);
        float c = -g_dinv[s] * ew[i] * g_dinv[d];
        g_pair[pos] = make_int2(s, __float_as_int(c));
    }
}

// ---------- K6: propagation px[dst] = sum coef * x[src], one warp per dst ----------
// Software-pipelined: prefetch next (src,coef) pair while FMA-ing current row.
__global__ void k_prop(const float* __restrict__ x, int n) {
    int gw = (blockIdx.x * blockDim.x + threadIdx.x) >> 5;
    int lane = threadIdx.x & 31;
    if (gw >= n) return;
    int start = g_offs[gw] + g_bpref[gw >> 10];
    int m = g_count[gw];
    float a0 = 0.f, a1 = 0.f;
    if (m > 0) {
        int2 sc = __ldg(&g_pair[start]);
        for (int j = 0; j < m; j++) {
            int2 nxt = __ldg(&g_pair[start + j + 1]);  // MAXE has +8 pad
            int s = sc.x;
            float c = __int_as_float(sc.y);
            const float* xr = x + (size_t)s * 64;
            a0 = fmaf(c, __ldg(&xr[lane]), a0);
            a1 = fmaf(c, __ldg(&xr[lane + 32]), a1);
            sc = nxt;
        }
    }
    g_px[(size_t)gw * 64 + lane] = a0;
    g_px[(size_t)gw * 64 + 32 + lane] = a1;
}

// ---------- K7: fused [x|px]@Wzh -> gate -> @Wlin -> L2-normalize ----------
#define TM 32
__global__ __launch_bounds__(256, 2) void k_fused(
    const float* __restrict__ x,
    const float* __restrict__ Wxz0, const float* __restrict__ Wxz1,
    const float* __restrict__ bxz,  const float* __restrict__ bhz,
    const float* __restrict__ Wxh0, const float* __restrict__ Wxh1,
    const float* __restrict__ bxh,  const float* __restrict__ bhh,
    const float* __restrict__ Wlin, const float* __restrict__ blin,
    float* __restrict__ out, int n)
{
    extern __shared__ __align__(16) float sh[];
    float* sW   = sh;                 // 128*128 = 16384
    float* sWl  = sW + 16384;         // 64*32   = 2048
    float* sB   = sWl + 2048;         // 128
    float* sBl  = sB + 128;           // 32
    float* sIN  = sBl + 32;           // 32*128  = 4096
    float* sU   = sIN + 4096;         // 32*64   = 2048
    // total 24736 floats = 98944 bytes

    int tid = threadIdx.x;

    for (int idx = tid; idx < 16384; idx += 256) {
        int k = idx >> 7, o = idx & 127;
        float v;
        if (k < 64) v = (o < 64) ? Wxz0[k * 64 + o] : Wxh0[k * 64 + (o - 64)];
        else        v = (o < 64) ? Wxz1[(k - 64) * 64 + o] : Wxh1[(k - 64) * 64 + (o - 64)];
        sW[idx] = v;
    }
    for (int idx = tid; idx < 2048; idx += 256) sWl[idx] = Wlin[idx];
    if (tid < 128) sB[tid] = (tid < 64) ? (bxz[tid] + bhz[tid]) : (bxh[tid - 64] + bhh[tid - 64]);
    if (tid < 32) sBl[tid] = blin[tid];

    int node0 = blockIdx.x * TM;

    for (int idx = tid; idx < TM * 32; idx += 256) {
        int r = idx >> 5, c4 = idx & 31;
        int node = node0 + r;
        float4 v = make_float4(0.f, 0.f, 0.f, 0.f);
        if (node < n) {
            if (c4 < 16) v = reinterpret_cast<const float4*>(x)[(size_t)node * 16 + c4];
            else         v = reinterpret_cast<const float4*>(g_px)[(size_t)node * 16 + (c4 - 16)];
        }
        reinterpret_cast<float4*>(sIN)[idx] = v;
    }
    __syncthreads();

    int og = tid & 31;
    int ng = tid >> 5;
    int obase = og * 4;
    float acc[4][4];
#pragma unroll
    for (int i = 0; i < 4; i++)
#pragma unroll
        for (int j = 0; j < 4; j++) acc[i][j] = sB[obase + j];

#pragma unroll 4
    for (int k = 0; k < 128; k++) {
        float4 w = *reinterpret_cast<const float4*>(&sW[k * 128 + obase]);
#pragma unroll
        for (int i = 0; i < 4; i++) {
            float in = sIN[(ng + i * 8) * 128 + k];
            acc[i][0] = fmaf(in, w.x, acc[i][0]);
            acc[i][1] = fmaf(in, w.y, acc[i][1]);
            acc[i][2] = fmaf(in, w.z, acc[i][2]);
            acc[i][3] = fmaf(in, w.w, acc[i][3]);
        }
    }
    __syncthreads();
#pragma unroll
    for (int i = 0; i < 4; i++) {
        int r = ng + i * 8;
#pragma unroll
        for (int j = 0; j < 4; j++) sIN[r * 128 + obase + j] = acc[i][j];
    }
    __syncthreads();

    for (int idx = tid; idx < TM * 64; idx += 256) {
        int r = idx >> 6, j = idx & 63;
        float zp = sIN[r * 128 + j];
        float hp = sIN[r * 128 + 64 + j];
        float z = 1.f / (1.f + __expf(-zp));
        sU[idx] = (1.f - z) * tanhf(hp);
    }
    __syncthreads();

    int node = tid >> 3;
    int og2 = tid & 7;
    int ob = og2 * 4;
    float a0 = sBl[ob], a1 = sBl[ob + 1], a2 = sBl[ob + 2], a3 = sBl[ob + 3];
#pragma unroll 8
    for (int k = 0; k < 64; k++) {
        float u = sU[node * 64 + k];
        float4 w = *reinterpret_cast<const float4*>(&sWl[k * 32 + ob]);
        a0 = fmaf(u, w.x, a0);
        a1 = fmaf(u, w.y, a1);
        a2 = fmaf(u, w.z, a2);
        a3 = fmaf(u, w.w, a3);
    }
    float ss = a0 * a0 + a1 * a1 + a2 * a2 + a3 * a3;
    ss += __shfl_xor_sync(0xffffffffu, ss, 1);
    ss += __shfl_xor_sync(0xffffffffu, ss, 2);
    ss += __shfl_xor_sync(0xffffffffu, ss, 4);
    float scale = 1.f / fmaxf(sqrtf(ss), 1e-12f);
    int gnode = node0 + node;
    if (gnode < n) {
        float4 o4 = make_float4(a0 * scale, a1 * scale, a2 * scale, a3 * scale);
        reinterpret_cast<float4*>(out)[(size_t)gnode * 8 + og2] = o4;
    }
}

extern "C" void kernel_launch(void* const* d_in, const int* in_sizes, int n_in,
                              void* d_out, int out_size) {
    const float* x    = (const float*)d_in[0];
    const void*  ei   = d_in[1];
    const float* ew   = (const float*)d_in[2];
    const float* Wxz0 = (const float*)d_in[3];
    const float* Wxz1 = (const float*)d_in[4];
    const float* bxz  = (const float*)d_in[5];
    const float* bhz  = (const float*)d_in[8];
    const float* Wxh0 = (const float*)d_in[15];
    const float* Wxh1 = (const float*)d_in[16];
    const float* bxh  = (const float*)d_in[17];
    const float* bhh  = (const float*)d_in[20];
    const float* Wlin = (const float*)d_in[21];
    const float* blin = (const float*)d_in[22];
    float* out = (float*)d_out;

    int n = in_sizes[0] / 64;   // 50000
    int e = in_sizes[2];        // 800000

    static int s_attr_done = 0;
    if (!s_attr_done) {
        cudaFuncSetAttribute(k_fused, cudaFuncAttributeMaxDynamicSharedMemorySize, 98944);
        s_attr_done = 1;
    }

    int nbN = (n + 255) / 256;
    int nbE = (e + 255) / 256;
    int nbScan = (n + 1023) / 1024;

    k_init<<<nbN, 256>>>((const int*)ei, n);            // #1
    k_edge1<<<nbE, 256>>>(ei, ew, e, n);                // #2
    k_scan_dinv<<<nbScan, 1024>>>(n);                   // #3
    k_scan_bsum<<<1, 64>>>(nbScan);                     // #4
    k_edge2<<<nbE, 256>>>(ei, ew, e, n);                // #5
    k_prop<<<(n * 32 + 255) / 256, 256>>>(x, n);        // #6  <- ncu -s 5 -c 1 window
    k_fused<<<(n + TM - 1) / TM, 256, 98944>>>(         // #7
        x, Wxz0, Wxz1, bxz, bhz, Wxh0, Wxh1, bxh, bhh, Wlin, blin, out, n);
}